// round 4
// baseline (speedup 1.0000x reference)
#include <cuda_runtime.h>
#include <math.h>

#define NMAX 100000

// ---------------- scratch (device globals: no allocation allowed) ----------
__device__ float4 g_h0[NMAX];           // normalized input features (x,y,area,0)
__device__ float4 g_agg0[NMAX];         // conv1 aggregate; .w accumulates degree
__device__ float4 g_h1[NMAX * 32];      // conv1 output      [node][128]
__device__ float4 g_agg1[NMAX * 32];    // conv2 aggregate   [node][128]
__device__ float4 g_h2[NMAX * 32];      // conv2 output      [node][128]
__device__ float  g_stats[16];          // reductions for _normalize
__device__ int    g_ei64;               // 1 if edge_index is int64, 0 if int32

__device__ __forceinline__ float finf() { return __int_as_float(0x7f800000); }

__device__ __forceinline__ void atomMaxF(float* addr, float v) {
    int old = __float_as_int(*addr);
    while (__int_as_float(old) < v) {
        int prev = atomicCAS((int*)addr, old, __float_as_int(v));
        if (prev == old) break;
        old = prev;
    }
}
__device__ __forceinline__ void atomMinF(float* addr, float v) {
    int old = __float_as_int(*addr);
    while (__int_as_float(old) > v) {
        int prev = atomicCAS((int*)addr, old, __float_as_int(v));
        if (prev == old) break;
        old = prev;
    }
}

// Fetch edge endpoint #i from a buffer of unknown (int32 vs int64) dtype.
__device__ __forceinline__ int edge_at(const int* ei32, int i) {
    return g_ei64 ? (int)((const long long*)ei32)[i] : ei32[i];
}

// ---------------- dtype probe: int64 edge data has zero high words ---------
__global__ void k_detect(const int* __restrict__ ei32) {
    if (threadIdx.x == 0 && blockIdx.x == 0) {
        int acc = 0;
        #pragma unroll
        for (int j = 0; j < 128; j++) acc |= ei32[2 * j + 1];
        g_ei64 = (acc == 0) ? 1 : 0;
    }
}

// ---------------- init: zero aggregates + reset stats ----------------------
__global__ void k_init(int n) {
    int i = blockIdx.x * blockDim.x + threadIdx.x;
    float4 z = make_float4(0.f, 0.f, 0.f, 0.f);
    if (i < n * 32) g_agg1[i] = z;
    if (i < n) g_agg0[i] = z;
    if (i == 0) {
        g_stats[0] = finf();  g_stats[1] = -finf();   // min/max x0
        g_stats[2] = finf();  g_stats[3] = -finf();   // min/max x1
        g_stats[4] = -finf();                          // max area
        g_stats[5] = 0.f;     g_stats[6] = 0.f;        // sum r0, sum r1
        g_stats[7] = -finf(); g_stats[8] = -finf();    // max r0, max r1
    }
}

// ---------------- normalize pass 1: min/max of raw coords, max area --------
__global__ void k_stats1(const float* __restrict__ x, int n) {
    int i = blockIdx.x * blockDim.x + threadIdx.x;
    float mn0 = finf(), mx0 = -finf(), mn1 = finf(), mx1 = -finf(), mxA = -finf();
    if (i < n) {
        float a = x[3 * i], b = x[3 * i + 1], c = x[3 * i + 2];
        mn0 = mx0 = a; mn1 = mx1 = b; mxA = c;
    }
    #pragma unroll
    for (int o = 16; o; o >>= 1) {
        mn0 = fminf(mn0, __shfl_xor_sync(0xffffffffu, mn0, o));
        mx0 = fmaxf(mx0, __shfl_xor_sync(0xffffffffu, mx0, o));
        mn1 = fminf(mn1, __shfl_xor_sync(0xffffffffu, mn1, o));
        mx1 = fmaxf(mx1, __shfl_xor_sync(0xffffffffu, mx1, o));
        mxA = fmaxf(mxA, __shfl_xor_sync(0xffffffffu, mxA, o));
    }
    if ((threadIdx.x & 31) == 0) {
        atomMinF(&g_stats[0], mn0); atomMaxF(&g_stats[1], mx0);
        atomMinF(&g_stats[2], mn1); atomMaxF(&g_stats[3], mx1);
        atomMaxF(&g_stats[4], mxA);
    }
}

// ---------------- normalize pass 2: (conditionally) rotate, sum & max ------
__global__ void k_rot(const float* __restrict__ x, int n) {
    int i = blockIdx.x * blockDim.x + threadIdx.x;
    bool rot = (g_stats[3] - g_stats[2]) > (g_stats[1] - g_stats[0]);
    float s0 = 0.f, s1 = 0.f, m0 = -finf(), m1 = -finf();
    if (i < n) {
        float a = x[3 * i], b = x[3 * i + 1], ar = x[3 * i + 2];
        float cc = cosf(1.5707964f);   // cos(float32(pi/2)) as jax computes it
        float ss = sinf(1.5707964f);
        float r0 = rot ? (cc * a - ss * b) : a;
        float r1 = rot ? (ss * a + cc * b) : b;
        g_h0[i] = make_float4(r0, r1, ar, 0.f);
        s0 = r0; s1 = r1; m0 = r0; m1 = r1;
    }
    #pragma unroll
    for (int o = 16; o; o >>= 1) {
        s0 += __shfl_xor_sync(0xffffffffu, s0, o);
        s1 += __shfl_xor_sync(0xffffffffu, s1, o);
        m0 = fmaxf(m0, __shfl_xor_sync(0xffffffffu, m0, o));
        m1 = fmaxf(m1, __shfl_xor_sync(0xffffffffu, m1, o));
    }
    if ((threadIdx.x & 31) == 0) {
        atomicAdd(&g_stats[5], s0); atomicAdd(&g_stats[6], s1);
        atomMaxF(&g_stats[7], m0);  atomMaxF(&g_stats[8], m1);
    }
}

// ---------------- normalize pass 3: center/scale ---------------------------
__global__ void k_norm(int n) {
    int i = blockIdx.x * blockDim.x + threadIdx.x;
    if (i >= n) return;
    float me0 = g_stats[5] / (float)n;
    float me1 = g_stats[6] / (float)n;
    float4 v = g_h0[i];
    v.x = (v.x - me0) / g_stats[7];
    v.y = (v.y - me1) / g_stats[8];
    v.z = v.z / g_stats[4];
    v.w = 0.f;
    g_h0[i] = v;
}

// ---------------- conv1 scatter: 3-dim messages + degree -------------------
__global__ void k_agg1(const int* __restrict__ ei, int nE, int n) {
    int i = blockIdx.x * blockDim.x + threadIdx.x;
    if (i >= nE) return;
    int s = edge_at(ei, i);
    int d = edge_at(ei, nE + i);
    s = min(max(s, 0), n - 1);
    d = min(max(d, 0), n - 1);
    float4 v = g_h0[s];
    float* dst = (float*)&g_agg0[d];
    atomicAdd(dst + 0, v.x);
    atomicAdd(dst + 1, v.y);
    atomicAdd(dst + 2, v.z);
    atomicAdd(dst + 3, 1.0f);
}

// ---------------- conv1 compute: h1 = tanh(Wl1*agg/deg + bl1 + Wr1*h0) -----
__global__ void k_conv1(const float* __restrict__ Wl, const float* __restrict__ bl,
                        const float* __restrict__ Wr, int n) {
    __shared__ float wl[384], wr[384], bb[128];
    int tid = threadIdx.x;
    if (tid < 128) bb[tid] = bl[tid];
    for (int j = tid; j < 384; j += blockDim.x) { wl[j] = Wl[j]; wr[j] = Wr[j]; }
    __syncthreads();
    int i = blockIdx.x * 2 + (tid >> 7);
    if (i >= n) return;
    int c = tid & 127;
    float4 ag = g_agg0[i];
    float inv = 1.0f / fmaxf(ag.w, 1.0f);
    float4 h = g_h0[i];
    float v = bb[c]
        + wl[c * 3 + 0] * (ag.x * inv) + wl[c * 3 + 1] * (ag.y * inv) + wl[c * 3 + 2] * (ag.z * inv)
        + wr[c * 3 + 0] * h.x + wr[c * 3 + 1] * h.y + wr[c * 3 + 2] * h.z;
    ((float*)g_h1)[i * 128 + c] = tanhf(v);
}

// ---------------- conv2 scatter: warp per edge, 4 floats per lane ----------
__global__ void k_agg2(const int* __restrict__ ei, int nE, int n) {
    int e = blockIdx.x * 8 + (threadIdx.x >> 5);
    if (e >= nE) return;
    int lane = threadIdx.x & 31;
    int s = edge_at(ei, e);
    int d = edge_at(ei, nE + e);
    s = min(max(s, 0), n - 1);
    d = min(max(d, 0), n - 1);
    float4 v = g_h1[s * 32 + lane];
    float* dst = (float*)&g_agg1[d * 32 + lane];
    atomicAdd(dst + 0, v.x);
    atomicAdd(dst + 1, v.y);
    atomicAdd(dst + 2, v.z);
    atomicAdd(dst + 3, v.w);
}

// ---------------- conv2 GEMM: h2 = tanh([agg/deg | h1] @ [Wl2|Wr2]^T + bl2)
__global__ __launch_bounds__(256) void k_conv2(const float* __restrict__ Wl,
        const float* __restrict__ bl, const float* __restrict__ Wr, int n) {
    extern __shared__ float sm[];
    float* Wc = sm;                    // [256][132]
    float* As = sm + 256 * 132;        // [64][256]
    float* bs = As + 64 * 256;         // [128]
    int tid = threadIdx.x;
    for (int idx = tid; idx < 128 * 256; idx += 256) {
        int c = idx >> 8;
        int k = idx & 255;
        float w = (k < 128) ? Wl[c * 128 + k] : Wr[c * 128 + (k - 128)];
        Wc[k * 132 + c] = w;
    }
    if (tid < 128) bs[tid] = bl[tid];
    int base = blockIdx.x * 64;
    for (int f = tid; f < 64 * 64; f += 256) {
        int nl = f >> 6;
        int kq = f & 63;
        int node = base + nl;
        float4 v = make_float4(0.f, 0.f, 0.f, 0.f);
        if (node < n) {
            if (kq < 32) {
                v = g_agg1[node * 32 + kq];
                float inv = 1.0f / fmaxf(g_agg0[node].w, 1.0f);
                v.x *= inv; v.y *= inv; v.z *= inv; v.w *= inv;
            } else {
                v = g_h1[node * 32 + (kq - 32)];
            }
        }
        ((float4*)As)[nl * 64 + kq] = v;
    }
    __syncthreads();
    int warp = tid >> 5, lane = tid & 31;
    const float* ap = As + warp * 8 * 256;
    int c0 = lane * 4;
    float acc[8][4];
    #pragma unroll
    for (int a = 0; a < 8; a++) { acc[a][0] = acc[a][1] = acc[a][2] = acc[a][3] = 0.f; }
    #pragma unroll 4
    for (int k = 0; k < 256; k++) {
        float4 w = *(const float4*)(Wc + k * 132 + c0);
        #pragma unroll
        for (int nn = 0; nn < 8; nn++) {
            float a = ap[nn * 256 + k];
            acc[nn][0] = fmaf(a, w.x, acc[nn][0]);
            acc[nn][1] = fmaf(a, w.y, acc[nn][1]);
            acc[nn][2] = fmaf(a, w.z, acc[nn][2]);
            acc[nn][3] = fmaf(a, w.w, acc[nn][3]);
        }
    }
    #pragma unroll
    for (int nn = 0; nn < 8; nn++) {
        int node = base + warp * 8 + nn;
        if (node < n) {
            float4 o;
            o.x = tanhf(acc[nn][0] + bs[c0 + 0]);
            o.y = tanhf(acc[nn][1] + bs[c0 + 1]);
            o.z = tanhf(acc[nn][2] + bs[c0 + 2]);
            o.w = tanhf(acc[nn][3] + bs[c0 + 3]);
            g_h2[node * 32 + lane] = o;
        }
    }
}

// ---------------- head: t = tanh(h2@W1^T+b1); out = softmax(t@W2^T+b2) -----
__global__ __launch_bounds__(256) void k_head(const float* __restrict__ W1,
        const float* __restrict__ b1, const float* __restrict__ W2,
        const float* __restrict__ b2, float* __restrict__ out, int n) {
    extern __shared__ float sm[];
    float* W1s = sm;                   // [128][260]
    float* As  = W1s + 128 * 260;      // [64][128]
    float* W2s = As + 64 * 128;        // [8][256]
    float* b1s = W2s + 2048;           // [256]
    float* b2s = b1s + 256;            // [8]
    int tid = threadIdx.x;
    for (int idx = tid; idx < 256 * 128; idx += 256) {
        int c = idx >> 7;
        int k = idx & 127;
        W1s[k * 260 + c] = W1[c * 128 + k];
    }
    for (int idx = tid; idx < 2048; idx += 256) W2s[idx] = W2[idx];
    b1s[tid] = b1[tid];
    if (tid < 8) b2s[tid] = b2[tid];
    int base = blockIdx.x * 64;
    for (int f = tid; f < 64 * 32; f += 256) {
        int nl = f >> 5, kq = f & 31;
        int node = base + nl;
        float4 v = make_float4(0.f, 0.f, 0.f, 0.f);
        if (node < n) v = g_h2[node * 32 + kq];
        ((float4*)As)[nl * 32 + kq] = v;
    }
    __syncthreads();
    int warp = tid >> 5, lane = tid & 31;
    const float* ap = As + warp * 8 * 128;
    int c0 = lane * 8;
    float acc[8][8];
    #pragma unroll
    for (int a = 0; a < 8; a++)
        #pragma unroll
        for (int b = 0; b < 8; b++) acc[a][b] = 0.f;
    #pragma unroll 2
    for (int k = 0; k < 128; k++) {
        float4 w0 = *(const float4*)(W1s + k * 260 + c0);
        float4 w1 = *(const float4*)(W1s + k * 260 + c0 + 4);
        #pragma unroll
        for (int nn = 0; nn < 8; nn++) {
            float a = ap[nn * 128 + k];
            acc[nn][0] = fmaf(a, w0.x, acc[nn][0]);
            acc[nn][1] = fmaf(a, w0.y, acc[nn][1]);
            acc[nn][2] = fmaf(a, w0.z, acc[nn][2]);
            acc[nn][3] = fmaf(a, w0.w, acc[nn][3]);
            acc[nn][4] = fmaf(a, w1.x, acc[nn][4]);
            acc[nn][5] = fmaf(a, w1.y, acc[nn][5]);
            acc[nn][6] = fmaf(a, w1.z, acc[nn][6]);
            acc[nn][7] = fmaf(a, w1.w, acc[nn][7]);
        }
    }
    float p[8][8];
    #pragma unroll
    for (int a = 0; a < 8; a++)
        #pragma unroll
        for (int b = 0; b < 8; b++) p[a][b] = 0.f;
    #pragma unroll
    for (int j = 0; j < 8; j++) {
        float bj = b1s[c0 + j];
        #pragma unroll
        for (int nn = 0; nn < 8; nn++) {
            float t = tanhf(acc[nn][j] + bj);
            #pragma unroll
            for (int c = 0; c < 8; c++)
                p[nn][c] = fmaf(t, W2s[c * 256 + c0 + j], p[nn][c]);
        }
    }
    #pragma unroll
    for (int o = 16; o; o >>= 1) {
        #pragma unroll
        for (int nn = 0; nn < 8; nn++)
            #pragma unroll
            for (int c = 0; c < 8; c++)
                p[nn][c] += __shfl_xor_sync(0xffffffffu, p[nn][c], o);
    }
    #pragma unroll
    for (int nn = 0; nn < 8; nn++) {
        if (lane == nn) {
            int node = base + warp * 8 + nn;
            if (node < n) {
                float l[8], m = -finf();
                #pragma unroll
                for (int c = 0; c < 8; c++) { l[c] = p[nn][c] + b2s[c]; m = fmaxf(m, l[c]); }
                float s = 0.f;
                #pragma unroll
                for (int c = 0; c < 8; c++) { l[c] = expf(l[c] - m); s += l[c]; }
                float inv = 1.0f / s;
                float4 o0 = make_float4(l[0] * inv, l[1] * inv, l[2] * inv, l[3] * inv);
                float4 o1 = make_float4(l[4] * inv, l[5] * inv, l[6] * inv, l[7] * inv);
                *(float4*)(out + node * 8) = o0;
                *(float4*)(out + node * 8 + 4) = o1;
            }
        }
    }
}

// ---------------- launch ---------------------------------------------------
// Inputs identified BY ELEMENT COUNT (order-agnostic). edge_index dtype
// (int32 vs int64 — JAX x64-disabled silently downgrades) probed on device.
extern "C" void kernel_launch(void* const* d_in, const int* in_sizes, int n_in,
                              void* d_out, int out_size) {
    const float* x = 0; const int* ei = 0;
    const float *Wl1 = 0, *bl1 = 0, *Wr1 = 0, *Wl2 = 0, *bl2 = 0, *Wr2 = 0;
    const float *W1 = 0, *b1 = 0, *W2 = 0, *b2 = 0;
    int n = 100000, nE = 600000;
    for (int i = 0; i < n_in; i++) {
        int sz = in_sizes[i];
        const void* p = d_in[i];
        switch (sz) {
            case 300000:  x  = (const float*)p; n  = sz / 3; break;
            case 1200000: ei = (const int*)p; nE = sz / 2; break;
            case 384:     if (!Wl1) Wl1 = (const float*)p; else Wr1 = (const float*)p; break;
            case 128:     if (!bl1) bl1 = (const float*)p; else bl2 = (const float*)p; break;
            case 16384:   if (!Wl2) Wl2 = (const float*)p; else Wr2 = (const float*)p; break;
            case 32768:   W1 = (const float*)p; break;
            case 256:     b1 = (const float*)p; break;
            case 2048:    W2 = (const float*)p; break;
            case 8:       b2 = (const float*)p; break;
            default: break;
        }
    }
    float* out = (float*)d_out;

    const int SMEM_CONV2 = (256 * 132 + 64 * 256 + 128) * 4;                 // 201216 B
    const int SMEM_HEAD  = (128 * 260 + 64 * 128 + 2048 + 256 + 8) * 4;      // 175136 B
    cudaFuncSetAttribute(k_conv2, cudaFuncAttributeMaxDynamicSharedMemorySize, SMEM_CONV2);
    cudaFuncSetAttribute(k_head,  cudaFuncAttributeMaxDynamicSharedMemorySize, SMEM_HEAD);

    k_detect<<<1, 32>>>(ei);
    k_init<<<(n * 32 + 255) / 256, 256>>>(n);
    int nb = (n + 255) / 256;
    k_stats1<<<nb, 256>>>(x, n);
    k_rot<<<nb, 256>>>(x, n);
    k_norm<<<nb, 256>>>(n);
    k_agg1<<<(nE + 255) / 256, 256>>>(ei, nE, n);
    k_conv1<<<(n + 1) / 2, 256>>>(Wl1, bl1, Wr1, n);
    k_agg2<<<(nE + 7) / 8, 256>>>(ei, nE, n);
    k_conv2<<<(n + 63) / 64, 256, SMEM_CONV2>>>(Wl2, bl2, Wr2, n);
    k_head<<<(n + 63) / 64, 256, SMEM_HEAD>>>(W1, b1, W2, b2, out, n);
}

// round 5
// speedup vs baseline: 1.1668x; 1.1668x over previous
#include <cuda_runtime.h>
#include <math.h>

#define NMAX 100000

// ---------------- scratch (device globals: no allocation allowed) ----------
__device__ float4 g_h0[NMAX];           // normalized input features (x,y,area,0)
__device__ float4 g_agg0[NMAX];         // conv1 aggregate; .w accumulates degree
__device__ float4 g_h1[NMAX * 32];      // conv1 output      [node][128]
__device__ float4 g_agg1[NMAX * 32];    // conv2 aggregate   [node][128]
__device__ float4 g_h2[NMAX * 32];      // conv2 output      [node][128]
__device__ float    g_stats[8];         // sums for _normalize
__device__ unsigned g_statu[8];         // encoded min/max: 0 mn0,1 mx0,2 mn1,3 mx1,4 mxA,5 mxr0,6 mxr1
__device__ int    g_ei64;               // 1 if edge_index is int64, 0 if int32

__device__ __forceinline__ float finf() { return __int_as_float(0x7f800000); }

// order-preserving float<->uint encode (atomicMin/Max on unsigned == float order)
__device__ __forceinline__ unsigned fenc(float f) {
    unsigned u = __float_as_uint(f);
    return u ^ ((unsigned)((int)u >> 31) | 0x80000000u);
}
__device__ __forceinline__ float fdec(unsigned e) {
    unsigned u = (e & 0x80000000u) ? (e ^ 0x80000000u) : ~e;
    return __uint_as_float(u);
}

// packed f32x2 helpers (Blackwell FFMA2 path — only reachable via PTX)
__device__ __forceinline__ unsigned long long pk2(float lo, float hi) {
    unsigned long long r;
    asm("mov.b64 %0, {%1, %2};" : "=l"(r) : "f"(lo), "f"(hi));
    return r;
}
__device__ __forceinline__ unsigned long long fma2(unsigned long long a,
        unsigned long long b, unsigned long long c) {
    unsigned long long d;
    asm("fma.rn.f32x2 %0, %1, %2, %3;" : "=l"(d) : "l"(a), "l"(b), "l"(c));
    return d;
}
__device__ __forceinline__ void upk2(float& lo, float& hi, unsigned long long v) {
    asm("mov.b64 {%0, %1}, %2;" : "=f"(lo), "=f"(hi) : "l"(v));
}

// vector reduction: one instruction adds 4 floats to global memory
__device__ __forceinline__ void red_add_v4(float4* addr, float a, float b, float c, float d) {
    unsigned long long ga = __cvta_generic_to_global(addr);
    asm volatile("red.global.add.v4.f32 [%0], {%1, %2, %3, %4};"
                 :: "l"(ga), "f"(a), "f"(b), "f"(c), "f"(d) : "memory");
}

// Fetch edge endpoint #i from a buffer of unknown (int32 vs int64) dtype.
__device__ __forceinline__ int edge_at(const int* ei32, int i) {
    return g_ei64 ? (int)((const long long*)ei32)[i] : ei32[i];
}

// ---------------- dtype probe: int64 edge data has zero high words ---------
__global__ void k_detect(const int* __restrict__ ei32) {
    if (threadIdx.x == 0 && blockIdx.x == 0) {
        int acc = 0;
        #pragma unroll
        for (int j = 0; j < 128; j++) acc |= ei32[2 * j + 1];
        g_ei64 = (acc == 0) ? 1 : 0;
    }
}

// ---------------- init: zero aggregates + reset stats ----------------------
__global__ void k_init(int n) {
    int i = blockIdx.x * blockDim.x + threadIdx.x;
    float4 z = make_float4(0.f, 0.f, 0.f, 0.f);
    if (i < n * 32) g_agg1[i] = z;
    if (i < n) g_agg0[i] = z;
    if (i == 0) {
        g_statu[0] = 0xFFFFFFFFu; g_statu[1] = 0u;   // min/max x0
        g_statu[2] = 0xFFFFFFFFu; g_statu[3] = 0u;   // min/max x1
        g_statu[4] = 0u;                              // max area
        g_statu[5] = 0u; g_statu[6] = 0u;             // max r0, r1
        g_stats[0] = 0.f; g_stats[1] = 0.f;           // sum r0, sum r1
    }
}

// ---------------- normalize pass 1: min/max of raw coords, max area --------
__global__ void k_stats1(const float* __restrict__ x, int n) {
    int i = blockIdx.x * blockDim.x + threadIdx.x;
    float mn0 = finf(), mx0 = -finf(), mn1 = finf(), mx1 = -finf(), mxA = -finf();
    if (i < n) {
        float a = x[3 * i], b = x[3 * i + 1], c = x[3 * i + 2];
        mn0 = mx0 = a; mn1 = mx1 = b; mxA = c;
    }
    #pragma unroll
    for (int o = 16; o; o >>= 1) {
        mn0 = fminf(mn0, __shfl_xor_sync(0xffffffffu, mn0, o));
        mx0 = fmaxf(mx0, __shfl_xor_sync(0xffffffffu, mx0, o));
        mn1 = fminf(mn1, __shfl_xor_sync(0xffffffffu, mn1, o));
        mx1 = fmaxf(mx1, __shfl_xor_sync(0xffffffffu, mx1, o));
        mxA = fmaxf(mxA, __shfl_xor_sync(0xffffffffu, mxA, o));
    }
    if ((threadIdx.x & 31) == 0) {
        atomicMin(&g_statu[0], fenc(mn0)); atomicMax(&g_statu[1], fenc(mx0));
        atomicMin(&g_statu[2], fenc(mn1)); atomicMax(&g_statu[3], fenc(mx1));
        atomicMax(&g_statu[4], fenc(mxA));
    }
}

// ---------------- normalize pass 2: (conditionally) rotate, sum & max ------
__global__ void k_rot(const float* __restrict__ x, int n) {
    int i = blockIdx.x * blockDim.x + threadIdx.x;
    bool rot = (fdec(g_statu[3]) - fdec(g_statu[2])) > (fdec(g_statu[1]) - fdec(g_statu[0]));
    float s0 = 0.f, s1 = 0.f, m0 = -finf(), m1 = -finf();
    if (i < n) {
        float a = x[3 * i], b = x[3 * i + 1], ar = x[3 * i + 2];
        float cc = cosf(1.5707964f);   // cos(float32(pi/2)) as jax computes it
        float ss = sinf(1.5707964f);
        float r0 = rot ? (cc * a - ss * b) : a;
        float r1 = rot ? (ss * a + cc * b) : b;
        g_h0[i] = make_float4(r0, r1, ar, 0.f);
        s0 = r0; s1 = r1; m0 = r0; m1 = r1;
    }
    #pragma unroll
    for (int o = 16; o; o >>= 1) {
        s0 += __shfl_xor_sync(0xffffffffu, s0, o);
        s1 += __shfl_xor_sync(0xffffffffu, s1, o);
        m0 = fmaxf(m0, __shfl_xor_sync(0xffffffffu, m0, o));
        m1 = fmaxf(m1, __shfl_xor_sync(0xffffffffu, m1, o));
    }
    if ((threadIdx.x & 31) == 0) {
        atomicAdd(&g_stats[0], s0); atomicAdd(&g_stats[1], s1);
        atomicMax(&g_statu[5], fenc(m0)); atomicMax(&g_statu[6], fenc(m1));
    }
}

// ---------------- normalize pass 3: center/scale ---------------------------
__global__ void k_norm(int n) {
    int i = blockIdx.x * blockDim.x + threadIdx.x;
    if (i >= n) return;
    float me0 = g_stats[0] / (float)n;
    float me1 = g_stats[1] / (float)n;
    float4 v = g_h0[i];
    v.x = (v.x - me0) / fdec(g_statu[5]);
    v.y = (v.y - me1) / fdec(g_statu[6]);
    v.z = v.z / fdec(g_statu[4]);
    v.w = 0.f;
    g_h0[i] = v;
}

// ---------------- conv1 scatter: 3-dim messages + degree -------------------
__global__ void k_agg1(const int* __restrict__ ei, int nE, int n) {
    int i = blockIdx.x * blockDim.x + threadIdx.x;
    if (i >= nE) return;
    int s = edge_at(ei, i);
    int d = edge_at(ei, nE + i);
    s = min(max(s, 0), n - 1);
    d = min(max(d, 0), n - 1);
    float4 v = g_h0[s];
    red_add_v4(&g_agg0[d], v.x, v.y, v.z, 1.0f);
}

// ---------------- conv1 compute: h1 = tanh(Wl1*agg/deg + bl1 + Wr1*h0) -----
__global__ void k_conv1(const float* __restrict__ Wl, const float* __restrict__ bl,
                        const float* __restrict__ Wr, int n) {
    __shared__ float wl[384], wr[384], bb[128];
    int tid = threadIdx.x;
    if (tid < 128) bb[tid] = bl[tid];
    for (int j = tid; j < 384; j += blockDim.x) { wl[j] = Wl[j]; wr[j] = Wr[j]; }
    __syncthreads();
    int i = blockIdx.x * 2 + (tid >> 7);
    if (i >= n) return;
    int c = tid & 127;
    float4 ag = g_agg0[i];
    float inv = 1.0f / fmaxf(ag.w, 1.0f);
    float4 h = g_h0[i];
    float v = bb[c]
        + wl[c * 3 + 0] * (ag.x * inv) + wl[c * 3 + 1] * (ag.y * inv) + wl[c * 3 + 2] * (ag.z * inv)
        + wr[c * 3 + 0] * h.x + wr[c * 3 + 1] * h.y + wr[c * 3 + 2] * h.z;
    ((float*)g_h1)[i * 128 + c] = tanhf(v);
}

// ---------------- conv2 scatter: warp per edge, one RED.128 per lane -------
__global__ void k_agg2(const int* __restrict__ ei, int nE, int n) {
    int e = blockIdx.x * 8 + (threadIdx.x >> 5);
    if (e >= nE) return;
    int lane = threadIdx.x & 31;
    int s = edge_at(ei, e);
    int d = edge_at(ei, nE + e);
    s = min(max(s, 0), n - 1);
    d = min(max(d, 0), n - 1);
    float4 v = g_h1[s * 32 + lane];
    red_add_v4(&g_agg1[d * 32 + lane], v.x, v.y, v.z, v.w);
}

// ---------------- conv2 GEMM: h2 = tanh([agg/deg | h1] @ [Wl2|Wr2]^T + bl2)
// FFMA2 mainloop: SIMD over channel pairs, accumulators in packed f32x2 regs.
__global__ __launch_bounds__(256) void k_conv2(const float* __restrict__ Wl,
        const float* __restrict__ bl, const float* __restrict__ Wr, int n) {
    extern __shared__ float sm[];
    float* Wc = sm;                    // [256][132]
    float* As = sm + 256 * 132;        // [64][256]
    float* bs = As + 64 * 256;         // [128]
    int tid = threadIdx.x;
    for (int idx = tid; idx < 128 * 256; idx += 256) {
        int c = idx >> 8;
        int k = idx & 255;
        float w = (k < 128) ? Wl[c * 128 + k] : Wr[c * 128 + (k - 128)];
        Wc[k * 132 + c] = w;
    }
    if (tid < 128) bs[tid] = bl[tid];
    int base = blockIdx.x * 64;
    for (int f = tid; f < 64 * 64; f += 256) {
        int nl = f >> 6;
        int kq = f & 63;
        int node = base + nl;
        float4 v = make_float4(0.f, 0.f, 0.f, 0.f);
        if (node < n) {
            if (kq < 32) {
                v = g_agg1[node * 32 + kq];
                float inv = 1.0f / fmaxf(g_agg0[node].w, 1.0f);
                v.x *= inv; v.y *= inv; v.z *= inv; v.w *= inv;
            } else {
                v = g_h1[node * 32 + (kq - 32)];
            }
        }
        ((float4*)As)[nl * 64 + kq] = v;
    }
    __syncthreads();
    int warp = tid >> 5, lane = tid & 31;
    const float* ap = As + warp * 8 * 256;
    int c0 = lane * 4;
    unsigned long long acc01[8], acc23[8];
    #pragma unroll
    for (int a = 0; a < 8; a++) { acc01[a] = 0ull; acc23[a] = 0ull; }
    #pragma unroll 4
    for (int k = 0; k < 256; k++) {
        float4 w = *(const float4*)(Wc + k * 132 + c0);
        unsigned long long w01 = pk2(w.x, w.y);
        unsigned long long w23 = pk2(w.z, w.w);
        #pragma unroll
        for (int nn = 0; nn < 8; nn++) {
            float a = ap[nn * 256 + k];
            unsigned long long a2 = pk2(a, a);
            acc01[nn] = fma2(a2, w01, acc01[nn]);
            acc23[nn] = fma2(a2, w23, acc23[nn]);
        }
    }
    #pragma unroll
    for (int nn = 0; nn < 8; nn++) {
        int node = base + warp * 8 + nn;
        if (node < n) {
            float a0, a1, a2, a3;
            upk2(a0, a1, acc01[nn]);
            upk2(a2, a3, acc23[nn]);
            float4 o;
            o.x = tanhf(a0 + bs[c0 + 0]);
            o.y = tanhf(a1 + bs[c0 + 1]);
            o.z = tanhf(a2 + bs[c0 + 2]);
            o.w = tanhf(a3 + bs[c0 + 3]);
            g_h2[node * 32 + lane] = o;
        }
    }
}

// ---------------- head: t = tanh(h2@W1^T+b1); out = softmax(t@W2^T+b2) -----
__global__ __launch_bounds__(256) void k_head(const float* __restrict__ W1,
        const float* __restrict__ b1, const float* __restrict__ W2,
        const float* __restrict__ b2, float* __restrict__ out, int n) {
    extern __shared__ float sm[];
    float* W1s = sm;                   // [128][260]
    float* As  = W1s + 128 * 260;      // [64][128]
    float* W2s = As + 64 * 128;        // [8][256]
    float* b1s = W2s + 2048;           // [256]
    float* b2s = b1s + 256;            // [8]
    int tid = threadIdx.x;
    for (int idx = tid; idx < 256 * 128; idx += 256) {
        int c = idx >> 7;
        int k = idx & 127;
        W1s[k * 260 + c] = W1[c * 128 + k];
    }
    for (int idx = tid; idx < 2048; idx += 256) W2s[idx] = W2[idx];
    b1s[tid] = b1[tid];
    if (tid < 8) b2s[tid] = b2[tid];
    int base = blockIdx.x * 64;
    for (int f = tid; f < 64 * 32; f += 256) {
        int nl = f >> 5, kq = f & 31;
        int node = base + nl;
        float4 v = make_float4(0.f, 0.f, 0.f, 0.f);
        if (node < n) v = g_h2[node * 32 + kq];
        ((float4*)As)[nl * 32 + kq] = v;
    }
    __syncthreads();
    int warp = tid >> 5, lane = tid & 31;
    const float* ap = As + warp * 8 * 128;
    int c0 = lane * 8;
    unsigned long long acc[8][4];
    #pragma unroll
    for (int a = 0; a < 8; a++)
        #pragma unroll
        for (int b = 0; b < 4; b++) acc[a][b] = 0ull;
    #pragma unroll 2
    for (int k = 0; k < 128; k++) {
        float4 w0 = *(const float4*)(W1s + k * 260 + c0);
        float4 w1 = *(const float4*)(W1s + k * 260 + c0 + 4);
        unsigned long long wp0 = pk2(w0.x, w0.y);
        unsigned long long wp1 = pk2(w0.z, w0.w);
        unsigned long long wp2 = pk2(w1.x, w1.y);
        unsigned long long wp3 = pk2(w1.z, w1.w);
        #pragma unroll
        for (int nn = 0; nn < 8; nn++) {
            float a = ap[nn * 128 + k];
            unsigned long long a2 = pk2(a, a);
            acc[nn][0] = fma2(a2, wp0, acc[nn][0]);
            acc[nn][1] = fma2(a2, wp1, acc[nn][1]);
            acc[nn][2] = fma2(a2, wp2, acc[nn][2]);
            acc[nn][3] = fma2(a2, wp3, acc[nn][3]);
        }
    }
    float p[8][8];
    #pragma unroll
    for (int a = 0; a < 8; a++)
        #pragma unroll
        for (int b = 0; b < 8; b++) p[a][b] = 0.f;
    #pragma unroll
    for (int nn = 0; nn < 8; nn++) {
        float t0[8];
        upk2(t0[0], t0[1], acc[nn][0]);
        upk2(t0[2], t0[3], acc[nn][1]);
        upk2(t0[4], t0[5], acc[nn][2]);
        upk2(t0[6], t0[7], acc[nn][3]);
        #pragma unroll
        for (int j = 0; j < 8; j++) {
            float t = tanhf(t0[j] + b1s[c0 + j]);
            #pragma unroll
            for (int c = 0; c < 8; c++)
                p[nn][c] = fmaf(t, W2s[c * 256 + c0 + j], p[nn][c]);
        }
    }
    #pragma unroll
    for (int o = 16; o; o >>= 1) {
        #pragma unroll
        for (int nn = 0; nn < 8; nn++)
            #pragma unroll
            for (int c = 0; c < 8; c++)
                p[nn][c] += __shfl_xor_sync(0xffffffffu, p[nn][c], o);
    }
    #pragma unroll
    for (int nn = 0; nn < 8; nn++) {
        if (lane == nn) {
            int node = base + warp * 8 + nn;
            if (node < n) {
                float l[8], m = -finf();
                #pragma unroll
                for (int c = 0; c < 8; c++) { l[c] = p[nn][c] + b2s[c]; m = fmaxf(m, l[c]); }
                float s = 0.f;
                #pragma unroll
                for (int c = 0; c < 8; c++) { l[c] = expf(l[c] - m); s += l[c]; }
                float inv = 1.0f / s;
                float4 o0 = make_float4(l[0] * inv, l[1] * inv, l[2] * inv, l[3] * inv);
                float4 o1 = make_float4(l[4] * inv, l[5] * inv, l[6] * inv, l[7] * inv);
                *(float4*)(out + node * 8) = o0;
                *(float4*)(out + node * 8 + 4) = o1;
            }
        }
    }
}

// ---------------- launch ---------------------------------------------------
// Inputs identified BY ELEMENT COUNT (order-agnostic). edge_index dtype
// (int32 vs int64) probed on device.
extern "C" void kernel_launch(void* const* d_in, const int* in_sizes, int n_in,
                              void* d_out, int out_size) {
    const float* x = 0; const int* ei = 0;
    const float *Wl1 = 0, *bl1 = 0, *Wr1 = 0, *Wl2 = 0, *bl2 = 0, *Wr2 = 0;
    const float *W1 = 0, *b1 = 0, *W2 = 0, *b2 = 0;
    int n = 100000, nE = 600000;
    for (int i = 0; i < n_in; i++) {
        int sz = in_sizes[i];
        const void* p = d_in[i];
        switch (sz) {
            case 300000:  x  = (const float*)p; n  = sz / 3; break;
            case 1200000: ei = (const int*)p; nE = sz / 2; break;
            case 384:     if (!Wl1) Wl1 = (const float*)p; else Wr1 = (const float*)p; break;
            case 128:     if (!bl1) bl1 = (const float*)p; else bl2 = (const float*)p; break;
            case 16384:   if (!Wl2) Wl2 = (const float*)p; else Wr2 = (const float*)p; break;
            case 32768:   W1 = (const float*)p; break;
            case 256:     b1 = (const float*)p; break;
            case 2048:    W2 = (const float*)p; break;
            case 8:       b2 = (const float*)p; break;
            default: break;
        }
    }
    float* out = (float*)d_out;

    const int SMEM_CONV2 = (256 * 132 + 64 * 256 + 128) * 4;                 // 201216 B
    const int SMEM_HEAD  = (128 * 260 + 64 * 128 + 2048 + 256 + 8) * 4;      // 175136 B
    cudaFuncSetAttribute(k_conv2, cudaFuncAttributeMaxDynamicSharedMemorySize, SMEM_CONV2);
    cudaFuncSetAttribute(k_head,  cudaFuncAttributeMaxDynamicSharedMemorySize, SMEM_HEAD);

    k_detect<<<1, 32>>>(ei);
    k_init<<<(n * 32 + 255) / 256, 256>>>(n);
    int nb = (n + 255) / 256;
    k_stats1<<<nb, 256>>>(x, n);
    k_rot<<<nb, 256>>>(x, n);
    k_norm<<<nb, 256>>>(n);
    k_agg1<<<(nE + 255) / 256, 256>>>(ei, nE, n);
    k_conv1<<<(n + 1) / 2, 256>>>(Wl1, bl1, Wr1, n);
    k_agg2<<<(nE + 7) / 8, 256>>>(ei, nE, n);
    k_conv2<<<(n + 63) / 64, 256, SMEM_CONV2>>>(Wl2, bl2, Wr2, n);
    k_head<<<(n + 63) / 64, 256, SMEM_HEAD>>>(W1, b1, W2, b2, out, n);
}